// round 1
// baseline (speedup 1.0000x reference)
#include <cuda_runtime.h>

// Implicit-GEMM conv2d, fp32.
//   C[m, n] = sum_k A[m, k] * B[k, n]
//   m = output channel (256), n = flattened (n_img, oh, ow) (32*56*56 = 100352)
//   k = flattened (c, r, s) (128*3*3 = 1152)
// A = W reshaped [256 x 1152] (OIHW is already row-major in k)
// B = im2col(x), materialized on the fly into shared memory with padding predication.

#define BM 128
#define BN 128
#define BK 16
#define PADB 132   // +4 floats padding; keeps rows 16B-aligned (132*4 = 528 = 33*16)

__global__ void __launch_bounds__(256, 2)
conv2d_igemm_kernel(const float* __restrict__ x,
                    const float* __restrict__ W,
                    const float* __restrict__ bias,
                    float* __restrict__ out)
{
    __shared__ float As[BK][PADB];  // [k][m]
    __shared__ float Bs[BK][PADB];  // [k][n]

    const int tid = threadIdx.x;
    const int tx = tid & 15;   // 0..15 -> n micro-tile
    const int ty = tid >> 4;   // 0..15 -> m micro-tile
    const int m0 = blockIdx.y * BM;
    const int n0 = blockIdx.x * BN;

    // ---- B-tile loader setup (one column of the tile per thread) ----
    const int bcol  = tid & 127;        // pixel column within tile
    const int brow0 = (tid >> 7) * 8;   // k rows 0..7 or 8..15
    const int pix   = n0 + bcol;
    const int n_img = pix / 3136;               // 3136 = 56*56
    const int rem   = pix - n_img * 3136;
    const int oh    = rem / 56;
    const int ow    = rem - oh * 56;
    const float* xb = x + (size_t)n_img * (128 * 3136) + oh * 56 + ow;

    float acc[8][8];
#pragma unroll
    for (int i = 0; i < 8; i++)
#pragma unroll
        for (int j = 0; j < 8; j++) acc[i][j] = 0.0f;

    for (int k0 = 0; k0 < 1152; k0 += BK) {
        // ---- load A tile: 128 oc-rows x 16 k-cols, 2 x float4 per thread ----
#pragma unroll
        for (int q = 0; q < 2; q++) {
            const int idx  = tid * 2 + q;
            const int row  = idx >> 2;        // 0..127 (oc within tile)
            const int col4 = (idx & 3) * 4;   // 0,4,8,12 (k within tile)
            const float4 v = *reinterpret_cast<const float4*>(
                W + (size_t)(m0 + row) * 1152 + k0 + col4);
            As[col4 + 0][row] = v.x;
            As[col4 + 1][row] = v.y;
            As[col4 + 2][row] = v.z;
            As[col4 + 3][row] = v.w;
        }

        // ---- load B tile: on-the-fly im2col with zero-padding predication ----
#pragma unroll
        for (int rr = 0; rr < 8; rr++) {
            const int k  = k0 + brow0 + rr;
            const int c  = k / 9;
            const int rs = k - c * 9;
            const int r  = rs / 3;
            const int s  = rs - r * 3;
            const int ih = oh + r - 1;
            const int iw = ow + s - 1;
            float v = 0.0f;
            if ((unsigned)ih < 56u && (unsigned)iw < 56u)
                v = __ldg(xb + c * 3136 + (r - 1) * 56 + (s - 1));
            Bs[brow0 + rr][bcol] = v;
        }
        __syncthreads();

        // ---- compute: 8x8 micro-tile per thread, split 4+4 to avoid conflicts ----
#pragma unroll
        for (int kk = 0; kk < BK; kk++) {
            float a[8], b[8];
            *reinterpret_cast<float4*>(a)     = *reinterpret_cast<const float4*>(&As[kk][ty * 4]);
            *reinterpret_cast<float4*>(a + 4) = *reinterpret_cast<const float4*>(&As[kk][64 + ty * 4]);
            *reinterpret_cast<float4*>(b)     = *reinterpret_cast<const float4*>(&Bs[kk][tx * 4]);
            *reinterpret_cast<float4*>(b + 4) = *reinterpret_cast<const float4*>(&Bs[kk][64 + tx * 4]);
#pragma unroll
            for (int i = 0; i < 8; i++)
#pragma unroll
                for (int j = 0; j < 8; j++)
                    acc[i][j] = fmaf(a[i], b[j], acc[i][j]);
        }
        __syncthreads();
    }

    // ---- epilogue: out[n_img, oc, oh, ow]; float4 stores unless a row of 4
    //      pixels straddles an image boundary (3136 is not a multiple of 128) ----
#pragma unroll
    for (int jb = 0; jb < 2; jb++) {
        const int nb = n0 + jb * 64 + tx * 4;       // first of 4 consecutive pixels
        const int ni = nb / 3136;
        const int rp = nb - ni * 3136;
        const bool vec_ok = (rp <= 3132);
#pragma unroll
        for (int ib = 0; ib < 2; ib++) {
#pragma unroll
            for (int ii = 0; ii < 4; ii++) {
                const int i  = ib * 4 + ii;
                const int m  = m0 + ib * 64 + ty * 4 + ii;
                const float bv = bias[m];
                if (vec_ok) {
                    float4 v;
                    v.x = acc[i][jb * 4 + 0] + bv;
                    v.y = acc[i][jb * 4 + 1] + bv;
                    v.z = acc[i][jb * 4 + 2] + bv;
                    v.w = acc[i][jb * 4 + 3] + bv;
                    *reinterpret_cast<float4*>(
                        out + (size_t)ni * (256 * 3136) + (size_t)m * 3136 + rp) = v;
                } else {
#pragma unroll
                    for (int j = 0; j < 4; j++) {
                        const int p   = nb + j;
                        const int ni2 = p / 3136;
                        const int rp2 = p - ni2 * 3136;
                        out[(size_t)ni2 * (256 * 3136) + (size_t)m * 3136 + rp2] =
                            acc[i][jb * 4 + j] + bv;
                    }
                }
            }
        }
    }
}

extern "C" void kernel_launch(void* const* d_in, const int* in_sizes, int n_in,
                              void* d_out, int out_size)
{
    const float* x    = (const float*)d_in[0];  // (32,128,56,56)
    const float* W    = (const float*)d_in[1];  // (256,128,3,3)
    const float* bias = (const float*)d_in[2];  // (256,)
    float* out        = (float*)d_out;          // (32,256,56,56)

    // N tiles = 100352/128 = 784, M tiles = 256/128 = 2
    dim3 grid(784, 2);
    conv2d_igemm_kernel<<<grid, 256>>>(x, W, bias, out);
}

// round 2
// speedup vs baseline: 1.0001x; 1.0001x over previous
#include <cuda_runtime.h>

// Implicit-GEMM conv2d, fp32.
//   C[m, n] = sum_k A[m, k] * B[k, n]
//   m = output channel (256), n = flattened (n_img, oh, ow) (32*56*56 = 100352)
//   k = flattened (c, r, s) (128*3*3 = 1152)
// A = W reshaped [256 x 1152] (OIHW is already row-major in k)
// B = im2col(x), materialized on the fly into shared memory with padding predication.

#define BM 128
#define BN 128
#define BK 16
#define PADB 132   // +4 floats padding; keeps rows 16B-aligned (132*4 = 528 = 33*16)

__global__ void __launch_bounds__(256, 2)
conv2d_igemm_kernel(const float* __restrict__ x,
                    const float* __restrict__ W,
                    const float* __restrict__ bias,
                    float* __restrict__ out)
{
    __shared__ float As[BK][PADB];  // [k][m]
    __shared__ float Bs[BK][PADB];  // [k][n]

    const int tid = threadIdx.x;
    const int tx = tid & 15;   // 0..15 -> n micro-tile
    const int ty = tid >> 4;   // 0..15 -> m micro-tile
    const int m0 = blockIdx.y * BM;
    const int n0 = blockIdx.x * BN;

    // ---- B-tile loader setup (one column of the tile per thread) ----
    const int bcol  = tid & 127;        // pixel column within tile
    const int brow0 = (tid >> 7) * 8;   // k rows 0..7 or 8..15
    const int pix   = n0 + bcol;
    const int n_img = pix / 3136;               // 3136 = 56*56
    const int rem   = pix - n_img * 3136;
    const int oh    = rem / 56;
    const int ow    = rem - oh * 56;
    const float* xb = x + (size_t)n_img * (128 * 3136) + oh * 56 + ow;

    float acc[8][8];
#pragma unroll
    for (int i = 0; i < 8; i++)
#pragma unroll
        for (int j = 0; j < 8; j++) acc[i][j] = 0.0f;

    for (int k0 = 0; k0 < 1152; k0 += BK) {
        // ---- load A tile: 128 oc-rows x 16 k-cols, 2 x float4 per thread ----
#pragma unroll
        for (int q = 0; q < 2; q++) {
            const int idx  = tid * 2 + q;
            const int row  = idx >> 2;        // 0..127 (oc within tile)
            const int col4 = (idx & 3) * 4;   // 0,4,8,12 (k within tile)
            const float4 v = *reinterpret_cast<const float4*>(
                W + (size_t)(m0 + row) * 1152 + k0 + col4);
            As[col4 + 0][row] = v.x;
            As[col4 + 1][row] = v.y;
            As[col4 + 2][row] = v.z;
            As[col4 + 3][row] = v.w;
        }

        // ---- load B tile: on-the-fly im2col with zero-padding predication ----
#pragma unroll
        for (int rr = 0; rr < 8; rr++) {
            const int k  = k0 + brow0 + rr;
            const int c  = k / 9;
            const int rs = k - c * 9;
            const int r  = rs / 3;
            const int s  = rs - r * 3;
            const int ih = oh + r - 1;
            const int iw = ow + s - 1;
            float v = 0.0f;
            if ((unsigned)ih < 56u && (unsigned)iw < 56u)
                v = __ldg(xb + c * 3136 + (r - 1) * 56 + (s - 1));
            Bs[brow0 + rr][bcol] = v;
        }
        __syncthreads();

        // ---- compute: 8x8 micro-tile per thread, split 4+4 to avoid conflicts ----
#pragma unroll
        for (int kk = 0; kk < BK; kk++) {
            float a[8], b[8];
            *reinterpret_cast<float4*>(a)     = *reinterpret_cast<const float4*>(&As[kk][ty * 4]);
            *reinterpret_cast<float4*>(a + 4) = *reinterpret_cast<const float4*>(&As[kk][64 + ty * 4]);
            *reinterpret_cast<float4*>(b)     = *reinterpret_cast<const float4*>(&Bs[kk][tx * 4]);
            *reinterpret_cast<float4*>(b + 4) = *reinterpret_cast<const float4*>(&Bs[kk][64 + tx * 4]);
#pragma unroll
            for (int i = 0; i < 8; i++)
#pragma unroll
                for (int j = 0; j < 8; j++)
                    acc[i][j] = fmaf(a[i], b[j], acc[i][j]);
        }
        __syncthreads();
    }

    // ---- epilogue: out[n_img, oc, oh, ow]; float4 stores unless a row of 4
    //      pixels straddles an image boundary (3136 is not a multiple of 128) ----
#pragma unroll
    for (int jb = 0; jb < 2; jb++) {
        const int nb = n0 + jb * 64 + tx * 4;       // first of 4 consecutive pixels
        const int ni = nb / 3136;
        const int rp = nb - ni * 3136;
        const bool vec_ok = (rp <= 3132);
#pragma unroll
        for (int ib = 0; ib < 2; ib++) {
#pragma unroll
            for (int ii = 0; ii < 4; ii++) {
                const int i  = ib * 4 + ii;
                const int m  = m0 + ib * 64 + ty * 4 + ii;
                const float bv = bias[m];
                if (vec_ok) {
                    float4 v;
                    v.x = acc[i][jb * 4 + 0] + bv;
                    v.y = acc[i][jb * 4 + 1] + bv;
                    v.z = acc[i][jb * 4 + 2] + bv;
                    v.w = acc[i][jb * 4 + 3] + bv;
                    *reinterpret_cast<float4*>(
                        out + (size_t)ni * (256 * 3136) + (size_t)m * 3136 + rp) = v;
                } else {
#pragma unroll
                    for (int j = 0; j < 4; j++) {
                        const int p   = nb + j;
                        const int ni2 = p / 3136;
                        const int rp2 = p - ni2 * 3136;
                        out[(size_t)ni2 * (256 * 3136) + (size_t)m * 3136 + rp2] =
                            acc[i][jb * 4 + j] + bv;
                    }
                }
            }
        }
    }
}

extern "C" void kernel_launch(void* const* d_in, const int* in_sizes, int n_in,
                              void* d_out, int out_size)
{
    const float* x    = (const float*)d_in[0];  // (32,128,56,56)
    const float* W    = (const float*)d_in[1];  // (256,128,3,3)
    const float* bias = (const float*)d_in[2];  // (256,)
    float* out        = (float*)d_out;          // (32,256,56,56)

    // N tiles = 100352/128 = 784, M tiles = 256/128 = 2
    dim3 grid(784, 2);
    conv2d_igemm_kernel<<<grid, 256>>>(x, W, bias, out);
}

// round 4
// speedup vs baseline: 3.5002x; 3.5000x over previous
#include <cuda_runtime.h>
#include <cstdint>

// Conv2d 3x3 s1 p1 via mma.sync tf32 implicit GEMM (legacy tensor path; the
// harness compiles to compute_103 PTX, which rejects all tcgen05/arch-'a' ops).
// GEMM: C[oc=256][px=100352] = Wt[1152][256]^T * im2col(x), K tap-major
// (k = rs*128 + c) so each 16-wide k-tile is a single tap -> dense shifted loads.

#define HW    3136
#define CIN   128
#define COUT  256
#define KTOT  1152
#define NKT   72
#define LDA   136                       // padded row stride (floats)
#define TILEF (16*LDA)                  // floats per A or B tile (2176)
#define STAGEF (2*TILEF)
#define NSTAGE 3
#define SMEM_BYTES (NSTAGE*STAGEF*4)    // 52224

__device__ float g_wt[KTOT * COUT];                       // [k][oc], tf32-rounded
__device__ __align__(16) float g_xt[64 + 32*CIN*HW + 64]; // x tf32-rounded, guard pads

// ---------------- prepass kernels ----------------
__global__ void wt_kernel(const float* __restrict__ W) {
    const int k = blockIdx.x;            // k = rs*128 + c
    const int oc = threadIdx.x;
    const int rs = k >> 7, c = k & 127;
    float v = W[oc * KTOT + c * 9 + rs];
    uint32_t t; asm("cvt.rna.tf32.f32 %0, %1;" : "=r"(t) : "f"(v));
    g_wt[k * COUT + oc] = __uint_as_float(t);
}

__global__ void xt_kernel(const float* __restrict__ x) {
    const int i = blockIdx.x * 256 + threadIdx.x;   // one float4 per thread
    float4 v = reinterpret_cast<const float4*>(x)[i];
    uint32_t a, b, c, d;
    asm("cvt.rna.tf32.f32 %0, %1;" : "=r"(a) : "f"(v.x));
    asm("cvt.rna.tf32.f32 %0, %1;" : "=r"(b) : "f"(v.y));
    asm("cvt.rna.tf32.f32 %0, %1;" : "=r"(c) : "f"(v.z));
    asm("cvt.rna.tf32.f32 %0, %1;" : "=r"(d) : "f"(v.w));
    float4 o = make_float4(__uint_as_float(a), __uint_as_float(b),
                           __uint_as_float(c), __uint_as_float(d));
    reinterpret_cast<float4*>(g_xt + 64)[i] = o;
}

// ---------------- cp.async helpers ----------------
__device__ __forceinline__ void cp16(uint32_t d, const void* s) {
    asm volatile("cp.async.cg.shared.global [%0], [%1], 16;" :: "r"(d), "l"(s));
}
__device__ __forceinline__ void cp4(uint32_t d, const void* s) {
    asm volatile("cp.async.ca.shared.global [%0], [%1], 4;" :: "r"(d), "l"(s));
}
#define CP_COMMIT asm volatile("cp.async.commit_group;" ::: "memory")
#define CP_WAIT1  asm volatile("cp.async.wait_group 1;" ::: "memory")

// ---------------- main kernel ----------------
__global__ void __launch_bounds__(128, 2)
conv_mma(const float* __restrict__ bias, float* __restrict__ out)
{
    extern __shared__ float sm[];
    const uint32_t smb = (uint32_t)__cvta_generic_to_shared(sm);
    const int tid  = threadIdx.x;
    const int lane = tid & 31;
    const int wid  = tid >> 5;                // 0..3
    const int r    = lane >> 2, cq = lane & 3;
    const int p0   = blockIdx.x * 128;        // pixel tile
    const int ni   = blockIdx.y;              // image
    const int m0   = blockIdx.z * 128;        // oc tile
    const int wm0  = (wid & 1) * 64;
    const int wn0  = (wid >> 1) * 64;
    const float* xb = g_xt + 64 + (size_t)ni * (CIN * HW);

    // B-loader thread mapping: 16 rows x 8 col-threads, cols ct + 8j (bank-spread)
    const int brow = tid >> 3;
    const int bct  = tid & 7;

    float acc[4][8][4];
#pragma unroll
    for (int mf = 0; mf < 4; mf++)
#pragma unroll
        for (int nf = 0; nf < 8; nf++)
#pragma unroll
            for (int e = 0; e < 4; e++) acc[mf][nf][e] = 0.0f;

    // ---- issue stage loads for k-tile kt ----
    auto issue = [&](int kt) {
        const int st = kt % NSTAGE;
        const uint32_t As = smb + st * (STAGEF * 4);
        const uint32_t Bs = As + TILEF * 4;
        // A: 16 rows x 128 oc, float4 cp.async (4 per thread)
#pragma unroll
        for (int q = 0; q < 4; q++) {
            const int idx = tid + q * 128;
            const int row = idx >> 5, col = (idx & 31) * 4;
            cp16(As + (row * LDA + col) * 4,
                 g_wt + (size_t)(kt * 16 + row) * COUT + m0 + col);
        }
        // B: tap-shifted x window, 16 rows (channels) x 128 px, 4B cp.async
        const int rs = kt >> 3, c0 = (kt & 7) * 16;
        const int rr = rs / 3, sc = rs - rr * 3;
        const int shift = (rr - 1) * 56 + (sc - 1);
        const float* src = xb + (size_t)(c0 + brow) * HW + p0 + shift + bct;
        const uint32_t dst = Bs + (brow * LDA + bct) * 4;
#pragma unroll
        for (int j = 0; j < 16; j++)
            cp4(dst + j * 32, src + j * 8);
    };

    issue(0); CP_COMMIT;
    issue(1); CP_COMMIT;

#pragma unroll 1
    for (int kt = 0; kt < NKT; kt++) {
        const int st = kt % NSTAGE;
        CP_WAIT1;
        __syncthreads();

        // ---- fixup: zero invalid (padding) pixel columns for this tap ----
        {
            const int rs = kt >> 3;
            const int rr = rs / 3, sc = rs - rr * 3;
            const int p = p0 + tid;
            const int oh = p / 56, ow = p - oh * 56;
            const bool bad = (rr == 0 && oh == 0) || (rr == 2 && oh == 55) ||
                             (sc == 0 && ow == 0) || (sc == 2 && ow == 55);
            if (bad && p < HW) {
                float* B = sm + st * STAGEF + TILEF;
#pragma unroll
                for (int row = 0; row < 16; row++) B[row * LDA + tid] = 0.0f;
            }
        }
        __syncthreads();

        if (kt + 2 < NKT) issue(kt + 2);
        CP_COMMIT;

        // ---- compute: 2 k8-steps, warp tile 64x64 (4 mf x 8 nf) ----
        const float* Asf = sm + st * STAGEF;
        const float* Bsf = Asf + TILEF;
#pragma unroll
        for (int ks = 0; ks < 2; ks++) {
            uint32_t a[4][4], b[8][2];
            const float* ap = Asf + (ks * 8 + cq) * LDA + wm0 + r;
#pragma unroll
            for (int mf = 0; mf < 4; mf++) {
                a[mf][0] = __float_as_uint(ap[mf * 16]);
                a[mf][1] = __float_as_uint(ap[mf * 16 + 8]);
                a[mf][2] = __float_as_uint(ap[4 * LDA + mf * 16]);
                a[mf][3] = __float_as_uint(ap[4 * LDA + mf * 16 + 8]);
            }
            const float* bp = Bsf + (ks * 8 + cq) * LDA + wn0 + r;
#pragma unroll
            for (int nf = 0; nf < 8; nf++) {
                b[nf][0] = __float_as_uint(bp[nf * 8]);
                b[nf][1] = __float_as_uint(bp[4 * LDA + nf * 8]);
            }
#pragma unroll
            for (int mf = 0; mf < 4; mf++)
#pragma unroll
                for (int nf = 0; nf < 8; nf++)
                    asm volatile(
                        "mma.sync.aligned.m16n8k8.row.col.f32.tf32.tf32.f32 "
                        "{%0,%1,%2,%3}, {%4,%5,%6,%7}, {%8,%9}, {%0,%1,%2,%3};"
                        : "+f"(acc[mf][nf][0]), "+f"(acc[mf][nf][1]),
                          "+f"(acc[mf][nf][2]), "+f"(acc[mf][nf][3])
                        : "r"(a[mf][0]), "r"(a[mf][1]), "r"(a[mf][2]), "r"(a[mf][3]),
                          "r"(b[nf][0]), "r"(b[nf][1]));
        }
    }

    // ---- epilogue: bias + store (float2, coalesced 32B per 4 lanes) ----
    const size_t obase = (size_t)ni * COUT * HW;
#pragma unroll
    for (int mf = 0; mf < 4; mf++) {
        const int mg = m0 + wm0 + mf * 16 + r;
        const float b0 = __ldg(bias + mg);
        const float b1 = __ldg(bias + mg + 8);
        float* o0 = out + obase + (size_t)mg * HW;
#pragma unroll
        for (int nf = 0; nf < 8; nf++) {
            const int px = p0 + wn0 + nf * 8 + cq * 2;
            if (px < HW) {
                float2 v0 = make_float2(acc[mf][nf][0] + b0, acc[mf][nf][1] + b0);
                float2 v1 = make_float2(acc[mf][nf][2] + b1, acc[mf][nf][3] + b1);
                *reinterpret_cast<float2*>(o0 + px) = v0;
                *reinterpret_cast<float2*>(o0 + (size_t)8 * HW + px) = v1;
            }
        }
    }
}

extern "C" void kernel_launch(void* const* d_in, const int* in_sizes, int n_in,
                              void* d_out, int out_size)
{
    const float* x    = (const float*)d_in[0];   // (32,128,56,56)
    const float* W    = (const float*)d_in[1];   // (256,128,3,3)
    const float* bias = (const float*)d_in[2];   // (256,)
    float* out        = (float*)d_out;           // (32,256,56,56)

    static bool attr_done = false;
    if (!attr_done) {
        cudaFuncSetAttribute(conv_mma, cudaFuncAttributeMaxDynamicSharedMemorySize,
                             SMEM_BYTES);
        attr_done = true;
    }

    wt_kernel<<<KTOT, COUT>>>(W);
    xt_kernel<<<12544, 256>>>(x);    // 12544*256 float4 = 12,845,056 floats

    dim3 grid(25, 32, 2);            // 25 px-tiles x 32 images x 2 oc-tiles
    conv_mma<<<grid, 128, SMEM_BYTES>>>(bias, out);
}